// round 1
// baseline (speedup 1.0000x reference)
#include <cuda_runtime.h>
#include <cstdint>

// ---------------------------------------------------------------------------
// QuadTreeDecoder
//   x: (128, 1, 64)
//   6 levels, NODES = {1,4,16,64,256,1024}, offsets {0,1,5,21,85,341}
//   per node p (level grid g x g):
//     lat[r]   = (sum_i x[b,p,i] * fi[p,r,i]) * scale[p,r]      (r=0..15)
//     child c in {tl,tr,bl,br}: out[o] = x[b,p,o] + sum_r lat[r]*Fc[p,r,o]
//     child node index: (2*gr + c/2)*(2g) + 2*gc + (c%2)
//   head: y[b,node,k] = dot(x[b,node,:], head_w[k,:]) + head_b[k], k=0..47
//   out[b][oc][sr*4+pr][sc*4+pc] = y[b, sr*64+sc, pr*12+pc*3+oc]
// ---------------------------------------------------------------------------

#define B_SZ 128

// ping-pong activation buffers (device globals: no allocation allowed)
__device__ float g_buf0[(size_t)B_SZ * 1024 * 64];   //  33.5 MB (levels 0,2,4 out)
__device__ float g_buf1[(size_t)B_SZ * 4096 * 64];   // 134 MB   (levels 1,3,5 out)

// ---------------------------------------------------------------------------
// Level kernel: one block per node, 128 threads = batch dim.
// ---------------------------------------------------------------------------
__global__ __launch_bounds__(128)
void qt_level_kernel(const float* __restrict__ xin, float* __restrict__ xout,
                     const float* __restrict__ fin,
                     const float* __restrict__ ftl, const float* __restrict__ ftr,
                     const float* __restrict__ fbl, const float* __restrict__ fbr,
                     const float* __restrict__ scale,
                     int n, int off, int gside)
{
    __shared__ float fi_s[16][64];       // [r][i]
    __shared__ float F_s[4][64][16];     // [child][o][r] (transposed for LDS.128 on r)
    __shared__ float sc_s[16];

    const int p   = blockIdx.x;
    const int tid = threadIdx.x;
    const int node = off + p;

    // stage factor_in
    const float* fib = fin + (size_t)node * 1024;
    for (int k = tid; k < 1024; k += 128)
        fi_s[k >> 6][k & 63] = fib[k];

    // stage the 4 out-factors, transposed (r,o)->(o,r)
    {
        const float* s0 = ftl + (size_t)node * 1024;
        const float* s1 = ftr + (size_t)node * 1024;
        const float* s2 = fbl + (size_t)node * 1024;
        const float* s3 = fbr + (size_t)node * 1024;
        for (int k = tid; k < 1024; k += 128) {
            int r = k >> 6, o = k & 63;
            F_s[0][o][r] = s0[k];
            F_s[1][o][r] = s1[k];
            F_s[2][o][r] = s2[k];
            F_s[3][o][r] = s3[k];
        }
    }
    if (tid < 16) sc_s[tid] = scale[(size_t)node * 16 + tid];
    __syncthreads();

    const int b = tid;
    const float* xp = xin + ((size_t)b * n + p) * 64;

    // x into registers
    float xr[64];
#pragma unroll
    for (int i = 0; i < 64; i += 4) {
        float4 v = *(const float4*)(xp + i);
        xr[i] = v.x; xr[i+1] = v.y; xr[i+2] = v.z; xr[i+3] = v.w;
    }

    // lat[r] = dot(x, fi[r,:]) * scale[r]
    float lat[16];
#pragma unroll
    for (int r = 0; r < 16; r++) {
        float a0 = 0.f, a1 = 0.f, a2 = 0.f, a3 = 0.f;
#pragma unroll
        for (int i = 0; i < 64; i += 4) {
            a0 += xr[i]     * fi_s[r][i];
            a1 += xr[i + 1] * fi_s[r][i + 1];
            a2 += xr[i + 2] * fi_s[r][i + 2];
            a3 += xr[i + 3] * fi_s[r][i + 3];
        }
        lat[r] = (a0 + a1 + a2 + a3) * sc_s[r];
    }

    const int gr = p / gside;
    const int gc = p - gr * gside;
    const int g2 = gside * 2;
    const size_t obase = (size_t)b * (4 * n);

#pragma unroll 1
    for (int c = 0; c < 4; c++) {
        const int cn = (2 * gr + (c >> 1)) * g2 + 2 * gc + (c & 1);
        float* op = xout + (obase + cn) * 64;
#pragma unroll 2
        for (int o = 0; o < 64; o += 4) {
            float4 acc = *(const float4*)(xp + o);   // residual (L1 hit)
#pragma unroll
            for (int r = 0; r < 16; r++) {
                float l = lat[r];
                acc.x += l * F_s[c][o + 0][r];
                acc.y += l * F_s[c][o + 1][r];
                acc.z += l * F_s[c][o + 2][r];
                acc.w += l * F_s[c][o + 3][r];
            }
            *(float4*)(op + o) = acc;
        }
    }
}

// ---------------------------------------------------------------------------
// Head kernel: thread per (b, node). 48 accumulators, head_w in smem.
// Writes directly into (B,3,256,256) layout, coalesced float4 per (oc,pr).
// grid = 128 * 16 blocks, 256 threads (node tile of 256).
// ---------------------------------------------------------------------------
__global__ __launch_bounds__(256)
void qt_head_kernel(const float* __restrict__ xin,
                    const float* __restrict__ head_w,
                    const float* __restrict__ head_b,
                    float* __restrict__ out)
{
    __shared__ float w_s[48][64];
    __shared__ float hb_s[48];

    const int tid = threadIdx.x;
    for (int k = tid; k < 48 * 64; k += 256)
        w_s[k >> 6][k & 63] = head_w[k];
    if (tid < 48) hb_s[tid] = head_b[tid];
    __syncthreads();

    const int b    = blockIdx.x >> 4;                  // 0..127
    const int node = ((blockIdx.x & 15) << 8) + tid;   // 0..4095

    float acc[48];
#pragma unroll
    for (int k = 0; k < 48; k++) acc[k] = hb_s[k];

    const float* xp = xin + ((size_t)b * 4096 + node) * 64;
#pragma unroll 2
    for (int i = 0; i < 64; i += 4) {
        float4 xv = *(const float4*)(xp + i);
#pragma unroll
        for (int k = 0; k < 48; k++) {
            acc[k] += xv.x * w_s[k][i]     + xv.y * w_s[k][i + 1]
                    + xv.z * w_s[k][i + 2] + xv.w * w_s[k][i + 3];
        }
    }

    const int sr = node >> 6, sc = node & 63;
#pragma unroll
    for (int oc = 0; oc < 3; oc++) {
#pragma unroll
        for (int pr = 0; pr < 4; pr++) {
            float4 v = make_float4(acc[pr * 12 + 0 + oc],
                                   acc[pr * 12 + 3 + oc],
                                   acc[pr * 12 + 6 + oc],
                                   acc[pr * 12 + 9 + oc]);
            size_t row = (size_t)(b * 3 + oc) * 256 + (sr * 4 + pr);
            *(float4*)(out + row * 256 + sc * 4) = v;
        }
    }
}

// ---------------------------------------------------------------------------
extern "C" void kernel_launch(void* const* d_in, const int* in_sizes, int n_in,
                              void* d_out, int out_size)
{
    const float* x      = (const float*)d_in[0];
    const float* fin    = (const float*)d_in[1];
    const float* ftl    = (const float*)d_in[2];
    const float* ftr    = (const float*)d_in[3];
    const float* fbl    = (const float*)d_in[4];
    const float* fbr    = (const float*)d_in[5];
    const float* scale  = (const float*)d_in[6];
    const float* head_w = (const float*)d_in[7];
    const float* head_b = (const float*)d_in[8];
    float* out = (float*)d_out;

    float *b0, *b1;
    cudaGetSymbolAddress((void**)&b0, g_buf0);
    cudaGetSymbolAddress((void**)&b1, g_buf1);

    const int   ns[6]   = {1, 4, 16, 64, 256, 1024};
    const int   offs[6] = {0, 1, 5, 21, 85, 341};
    const int   gs[6]   = {1, 2, 4, 8, 16, 32};

    const float* cur = x;
    for (int l = 0; l < 6; l++) {
        float* o = (l & 1) ? b1 : b0;
        qt_level_kernel<<<ns[l], 128>>>(cur, o, fin, ftl, ftr, fbl, fbr, scale,
                                        ns[l], offs[l], gs[l]);
        cur = o;
    }

    qt_head_kernel<<<128 * 16, 256>>>(cur, head_w, head_b, out);
}